// round 16
// baseline (speedup 1.0000x reference)
#include <cuda_runtime.h>
#include <cstdint>

#define NSTEPS   730
#define NGRID    8000
#define UHL      15
#define CH       10          // timesteps per chunk; 730 = 73 * 10
#define NCHUNK   (NSTEPS / CH)
#define CELLS    64          // cells per block
#define BT       192         // 6 warps: 0-1 snow, 2-3 soil, 4-5 router
#define SBN      3           // input staging buffers
#define NEARZERO 1e-5f

__device__ __forceinline__ float ex2_(float x) {
    float r; asm("ex2.approx.ftz.f32 %0, %1;" : "=f"(r) : "f"(x)); return r;
}
__device__ __forceinline__ float lg2_(float x) {
    float r; asm("lg2.approx.ftz.f32 %0, %1;" : "=f"(r) : "f"(x)); return r;
}
__device__ __forceinline__ float sigmoidf_(float x) {
    return 1.0f / (1.0f + __expf(-x));
}

__device__ __forceinline__ uint32_t smem_u32(const void* p) {
    uint32_t a;
    asm("{ .reg .u64 t; cvta.to.shared.u64 t, %1; cvt.u32.u64 %0, t; }" : "=r"(a) : "l"(p));
    return a;
}
__device__ __forceinline__ void cp_async16(uint32_t dst, const void* src) {
    asm volatile("cp.async.ca.shared.global [%0], [%1], 16;\n" :: "r"(dst), "l"(src));
}
__device__ __forceinline__ void cp_commit() { asm volatile("cp.async.commit_group;\n"); }
__device__ __forceinline__ void cp_wait1() { asm volatile("cp.async.wait_group 1;\n"); }

// input staging (snow reads): [SBN][CH][CELLS*3] = 22.5 KB
__shared__ float sbuf[SBN][CH][CELLS * 3];
// snow -> soil ring: (rt, PET) per cell: [2][CH][CELLS*2] = 10 KB
__shared__ float rtring[2][CH][CELLS * 2];
// soil -> router ring: (Q0,Q1,Q2) per cell: [2][CH][CELLS*3] = 15 KB
__shared__ float qring[2][CH][CELLS * 3];

// cooperative over the 64 snow threads (tid 0..63)
__device__ __forceinline__ void issue_chunk(const float* __restrict__ xphy,
                                            int c, int g0, int tid,
                                            uint32_t sbase) {
    const int t0 = c * CH;
    const int pb = c % SBN;
    constexpr int ROW16 = CELLS * 3 / 4;     // 48 16B units per row
    constexpr int TOT16 = CH * ROW16;        // 480
    #pragma unroll 1
    for (int idx = tid; idx < TOT16; idx += CELLS) {
        int row = idx / ROW16;
        int col = idx - row * ROW16;
        const float* src = xphy + ((size_t)(t0 + row) * NGRID + (size_t)g0) * 3 + col * 4;
        uint32_t dst = sbase + (uint32_t)(((pb * CH + row) * (CELLS * 3) + col * 4) * 4);
        cp_async16(dst, src);
    }
    cp_commit();
}

__global__ __launch_bounds__(BT, 1)
void hbv_kernel(const float* __restrict__ xphy,    // [T, G, 3]
                const float* __restrict__ params,  // [T, G, 16]
                float*       __restrict__ out)     // [T, G, 4]
{
    const int tid = threadIdx.x;
    const int wid = tid >> 5;
    const int g0  = blockIdx.x * CELLS;
    const uint32_t sbase = smem_u32(&sbuf[0][0][0]);

    if (wid < 2) {
        // ================= STAGE 1: SNOW (warps 0-1, SMSP 0-1) =================
        const int cidx = tid;                 // 0..63
        const int g    = g0 + cidx;
        const float* pr = params + ((size_t)(NSTEPS - 1) * NGRID + (size_t)g) * 16;
        float4 r2 = *(const float4*)(pr + 8);
        const float parTT    = -2.5f + sigmoidf_(r2.x) * 5.0f;
        const float parCFMAX = 0.5f  + sigmoidf_(r2.y) * 9.5f;
        const float parCFR   =         sigmoidf_(r2.z) * 0.1f;
        const float parCWH   =         sigmoidf_(r2.w) * 0.2f;

        float SP = 0.001f, MW = 0.001f;
        const int c3 = cidx * 3, c2 = cidx * 2;

        issue_chunk(xphy, 0, g0, tid, sbase);
        issue_chunk(xphy, 1, g0, tid, sbase);

        for (int k = 0; k <= NCHUNK + 1; k++) {
            if (k < NCHUNK) cp_wait1();       // chunk k copies (this thread's) done
            __syncthreads();                  // publish copies + ring handoff
            if (k >= NCHUNK) continue;
            if (k + 2 < NCHUNK)
                issue_chunk(xphy, k + 2, g0, tid, sbase);  // buffer (k+2)%3 free now
            else
                cp_commit();                  // dummy group keeps wait accounting

            const int sb = k % SBN;
            const int rb = k & 1;
            #pragma unroll
            for (int u = 0; u < CH; u++) {
                const float P   = sbuf[sb][u][c3 + 0];
                const float Tt  = sbuf[sb][u][c3 + 1];
                const float PET = sbuf[sb][u][c3 + 2];

                // merged melt/refreeze (mutually exclusive by sign of d)
                const float d    = Tt - parTT;
                const float RAIN = (d >= 0.0f) ? P : 0.0f;
                const float SNOW = (d <  0.0f) ? P : 0.0f;
                const float md   = parCFMAX * d;
                const float xr   = fmaxf(md, parCFR * md);
                const float sp0  = SP + SNOW;
                const float x    = fminf(fmaxf(xr, -MW), sp0);
                const float sp1  = sp0 - x;
                const float mw1  = MW + x;
                const float tosoil = fmaxf(fmaf(-parCWH, sp1, mw1), 0.0f);
                MW = mw1 - tosoil;
                SP = sp1;

                rtring[rb][u][c2 + 0] = RAIN + tosoil;
                rtring[rb][u][c2 + 1] = PET;
            }
        }
    } else if (wid < 4) {
        // ================= STAGE 2: SOIL (warps 2-3, SMSP 2-3, critical) =======
        const int cidx = tid - 64;            // 0..63
        const int g    = g0 + cidx;
        const float* pr = params + ((size_t)(NSTEPS - 1) * NGRID + (size_t)g) * 16;
        float4 r0 = *(const float4*)(pr + 0);
        float4 r1 = *(const float4*)(pr + 4);
        float4 r3 = *(const float4*)(pr + 12);

        const float parBETA   = 1.0f   + sigmoidf_(r0.x) * 5.0f;
        const float parFC     = 50.0f  + sigmoidf_(r0.y) * 950.0f;
        const float parK0     = 0.05f  + sigmoidf_(r0.z) * 0.85f;
        const float parK1     = 0.01f  + sigmoidf_(r0.w) * 0.49f;
        const float parK2     = 0.001f + sigmoidf_(r1.x) * 0.199f;
        const float parLP     = 0.2f   + sigmoidf_(r1.y) * 0.8f;
        const float parPERC   =          sigmoidf_(r1.z) * 10.0f;
        const float parUZL    =          sigmoidf_(r1.w) * 100.0f;
        const float parBETAET = 0.3f   + sigmoidf_(r3.x) * 4.7f;
        const float parC      =          sigmoidf_(r3.y);

        const float inv_fc   = __fdividef(1.0f, parFC);
        const float nBlg2FC  = -parBETA   * lg2_(parFC);
        const float nBElg2LP = -parBETAET * lg2_(parLP * parFC);
        const float k0uzl    = parK0 * parUZL;

        float SM = 0.001f, SUZ = 0.001f, SLZ = 0.001f;
        float sw = fminf(ex2_(fmaf(parBETA, lg2_(SM), nBlg2FC)), 1.0f);
        float pQ0 = 0.0f, pQ1 = 0.0f, pQ2 = 0.0f;
        const int c2 = cidx * 2, c3 = cidx * 3;

        for (int k = 0; k <= NCHUNK + 1; k++) {
            __syncthreads();
            if (k < 1 || k > NCHUNK) continue;
            const int c  = k - 1;             // chunk to process
            const int rb = c & 1;
            const int qb = c & 1;

            // batch-load this chunk's forcings into registers (MLP, no per-step LDS)
            float rtv[CH], pev[CH];
            #pragma unroll
            for (int u = 0; u < CH; u++) {
                rtv[u] = rtring[rb][u][c2 + 0];
                pev[u] = rtring[rb][u][c2 + 1];
            }

            #pragma unroll
            for (int u = 0; u < CH; u++) {
                const float rt  = rtv[u];
                const float PET = pev[u];

                // ---- soil moisture (sw carried from previous step) ----
                const float recharge = rt * sw;
                const float SM1 = fmaf(-rt, sw, SM + rt);
                const float excess = fmaxf(SM1 - parFC, 0.0f);
                const float SM2 = fminf(SM1, parFC);
                // capillary (min-with-SLZ redundant: C<=1 and SM2<=FC)
                const float cap  = (parC * SLZ) * fmaf(-inv_fc, SM2, 1.0f);
                const float SM3  = fmaxf(SM2 + cap, NEARZERO);
                const float SLZa = fmaxf(SLZ - cap, NEARZERO);

                // ---- evapfactor pow ----
                const float ef_raw = ex2_(fmaf(parBETAET, lg2_(SM3), nBElg2LP));

                // ==== FILL pow shadow: publish PREVIOUS step's Qs ====
                if (u > 0) {
                    qring[qb][u - 1][c3 + 0] = pQ0;
                    qring[qb][u - 1][c3 + 1] = pQ1;
                    qring[qb][u - 1][c3 + 2] = pQ2;
                }

                // ---- ET & SM (min(ET,SM3) folded into outer max) ----
                const float ef = fminf(ef_raw, 1.0f);
                SM = fmaxf(fmaf(-PET, ef, SM3), NEARZERO);

                // ---- next step's soil-wetness pow ----
                sw = fminf(ex2_(fmaf(parBETA, lg2_(SM), nBlg2FC)), 1.0f);

                // ==== FILL: response routine (independent of sw) ====
                float suz = SUZ + recharge + excess;
                const float perc = fminf(suz, parPERC);
                suz -= perc;
                const float Q0 = fmaxf(fmaf(parK0, suz, -k0uzl), 0.0f);
                suz -= Q0;
                const float Q1 = parK1 * suz;
                SUZ = suz - Q1;
                float slz = SLZa + perc;
                const float Q2 = parK2 * slz;
                SLZ = slz - Q2;

                pQ0 = Q0; pQ1 = Q1; pQ2 = Q2;
            }
            // flush final step of this chunk
            qring[qb][CH - 1][c3 + 0] = pQ0;
            qring[qb][CH - 1][c3 + 1] = pQ1;
            qring[qb][CH - 1][c3 + 2] = pQ2;
        }
    } else {
        // ================= STAGE 3: ROUTER (warps 4-5, SMSP 0-1) ===============
        const int cidx = tid - 128;           // 0..63
        const int g    = g0 + cidx;
        const float* pr = params + ((size_t)(NSTEPS - 1) * NGRID + (size_t)g) * 16;
        float4 r3 = *(const float4*)(pr + 12);
        const float route_a = sigmoidf_(r3.z) * 2.9f;
        const float route_b = sigmoidf_(r3.w) * 6.5f;
        const float aa    = fmaxf(route_a, 0.0f) + 0.1f;
        const float theta = fmaxf(route_b, 0.0f) + 0.5f;
        const float am1   = aa - 1.0f;
        const float invth = __fdividef(1.0f, theta);

        float w[UHL];
        float wsum = 0.0f;
        #pragma unroll
        for (int k = 0; k < UHL; k++) {
            float tk = (float)k + 0.5f;
            float v  = __expf(am1 * __logf(tk) - tk * invth);
            w[k] = v;
            wsum += v;
        }
        const float inv_wsum = __fdividef(1.0f, wsum);
        #pragma unroll
        for (int k = 0; k < UHL; k++) w[k] *= inv_wsum;

        float a0[UHL - 1], a1[UHL - 1], a2[UHL - 1];
        #pragma unroll
        for (int j = 0; j < UHL - 1; j++) { a0[j] = 0.0f; a1[j] = 0.0f; a2[j] = 0.0f; }

        float4* __restrict__ out4 = (float4*)out;
        const int c3 = cidx * 3;

        for (int k = 0; k <= NCHUNK + 1; k++) {
            __syncthreads();
            if (k < 2) continue;
            const int c  = k - 2;
            const int qb = c & 1;
            const int t0 = c * CH;

            #pragma unroll
            for (int u = 0; u < CH; u++) {
                const float q0 = qring[qb][u][c3 + 0];
                const float q1 = qring[qb][u][c3 + 1];
                const float q2 = qring[qb][u][c3 + 2];

                const float y0 = a0[0] + w[0] * q0;
                const float y1 = a1[0] + w[0] * q1;
                const float y2 = a2[0] + w[0] * q2;
                #pragma unroll
                for (int j = 0; j < UHL - 2; j++) {
                    a0[j] = a0[j + 1] + w[j + 1] * q0;
                    a1[j] = a1[j + 1] + w[j + 1] * q1;
                    a2[j] = a2[j + 1] + w[j + 1] * q2;
                }
                a0[UHL - 2] = w[UHL - 1] * q0;
                a1[UHL - 2] = w[UHL - 1] * q1;
                a2[UHL - 2] = w[UHL - 1] * q2;

                float4 o;
                o.x = y0 + y1 + y2;
                o.y = y0;
                o.z = y1;
                o.w = y2;
                out4[(size_t)(t0 + u) * NGRID + g] = o;
            }
        }
    }
}

extern "C" void kernel_launch(void* const* d_in, const int* in_sizes, int n_in,
                              void* d_out, int out_size) {
    const float* xphy   = (const float*)d_in[0];   // [730, 8000, 3]
    const float* params = (const float*)d_in[1];   // [730, 8000, 16]
    float* out = (float*)d_out;                    // [730, 8000, 4]
    (void)in_sizes; (void)n_in; (void)out_size;

    dim3 block(BT);
    dim3 grid(NGRID / CELLS);   // 125 blocks: 6 warps each, 1 block per SM
    hbv_kernel<<<grid, block>>>(xphy, params, out);
}

// round 17
// speedup vs baseline: 1.4410x; 1.4410x over previous
#include <cuda_runtime.h>
#include <cstdint>

#define NSTEPS   730
#define NGRID    8000
#define UHL      15
#define CH       10          // timesteps per chunk; 730 = 73 * 10
#define NCHUNK   (NSTEPS / CH)
#define CELLS    64          // cells per block
#define BT       128         // 4 warps: 0-1 producer (snow+soil), 2-3 router (+staging)
#define SBN      3           // input staging buffers
#define NEARZERO 1e-5f

__device__ __forceinline__ float ex2_(float x) {
    float r; asm("ex2.approx.ftz.f32 %0, %1;" : "=f"(r) : "f"(x)); return r;
}
__device__ __forceinline__ float lg2_(float x) {
    float r; asm("lg2.approx.ftz.f32 %0, %1;" : "=f"(r) : "f"(x)); return r;
}
__device__ __forceinline__ float sigmoidf_(float x) {
    return 1.0f / (1.0f + __expf(-x));
}

__device__ __forceinline__ uint32_t smem_u32(const void* p) {
    uint32_t a;
    asm("{ .reg .u64 t; cvta.to.shared.u64 t, %1; cvt.u32.u64 %0, t; }" : "=r"(a) : "l"(p));
    return a;
}
__device__ __forceinline__ void cp_async16(uint32_t dst, const void* src) {
    asm volatile("cp.async.ca.shared.global [%0], [%1], 16;\n" :: "r"(dst), "l"(src));
}
__device__ __forceinline__ void cp_commit() { asm volatile("cp.async.commit_group;\n"); }
__device__ __forceinline__ void cp_wait1() { asm volatile("cp.async.wait_group 1;\n"); }

// input staging: [SBN][CH][CELLS*3] = 22.5 KB  (written by router warps)
__shared__ float sbuf[SBN][CH][CELLS * 3];
// Q handoff ring (producer -> router): [2][CH][CELLS*3] = 15 KB
__shared__ float qring[2][CH][CELLS * 3];

// cooperative over the 64 router threads (cidx 0..63)
__device__ __forceinline__ void issue_chunk(const float* __restrict__ xphy,
                                            int c, int g0, int cidx,
                                            uint32_t sbase) {
    const int t0 = c * CH;
    const int pb = c % SBN;
    constexpr int ROW16 = CELLS * 3 / 4;     // 48 16B units per row
    constexpr int TOT16 = CH * ROW16;        // 480
    #pragma unroll 1
    for (int idx = cidx; idx < TOT16; idx += CELLS) {
        int row = idx / ROW16;
        int col = idx - row * ROW16;
        const float* src = xphy + ((size_t)(t0 + row) * NGRID + (size_t)g0) * 3 + col * 4;
        uint32_t dst = sbase + (uint32_t)(((pb * CH + row) * (CELLS * 3) + col * 4) * 4);
        cp_async16(dst, src);
    }
    cp_commit();
}

__global__ __launch_bounds__(BT, 1)
void hbv_kernel(const float* __restrict__ xphy,    // [T, G, 3]
                const float* __restrict__ params,  // [T, G, 16]
                float*       __restrict__ out)     // [T, G, 4]
{
    const int tid = threadIdx.x;
    const int wid = tid >> 5;
    const int g0  = blockIdx.x * CELLS;
    const uint32_t sbase = smem_u32(&sbuf[0][0][0]);

    if (wid < 2) {
        // ============ PRODUCER: snow + soil recurrence (SMSP 0-1) ============
        const int cidx = tid;                 // 0..63
        const int g    = g0 + cidx;
        const float* pr = params + ((size_t)(NSTEPS - 1) * NGRID + (size_t)g) * 16;
        float4 r0 = *(const float4*)(pr + 0);
        float4 r1 = *(const float4*)(pr + 4);
        float4 r2 = *(const float4*)(pr + 8);
        float4 r3 = *(const float4*)(pr + 12);

        const float parBETA   = 1.0f   + sigmoidf_(r0.x) * 5.0f;
        const float parFC     = 50.0f  + sigmoidf_(r0.y) * 950.0f;
        const float parK0     = 0.05f  + sigmoidf_(r0.z) * 0.85f;
        const float parK1     = 0.01f  + sigmoidf_(r0.w) * 0.49f;
        const float parK2     = 0.001f + sigmoidf_(r1.x) * 0.199f;
        const float parLP     = 0.2f   + sigmoidf_(r1.y) * 0.8f;
        const float parPERC   =          sigmoidf_(r1.z) * 10.0f;
        const float parUZL    =          sigmoidf_(r1.w) * 100.0f;
        const float parTT     = -2.5f  + sigmoidf_(r2.x) * 5.0f;
        const float parCFMAX  = 0.5f   + sigmoidf_(r2.y) * 9.5f;
        const float parCFR    =          sigmoidf_(r2.z) * 0.1f;
        const float parCWH    =          sigmoidf_(r2.w) * 0.2f;
        const float parBETAET = 0.3f   + sigmoidf_(r3.x) * 4.7f;
        const float parC      =          sigmoidf_(r3.y);

        const float inv_fc   = __fdividef(1.0f, parFC);
        const float nBlg2FC  = -parBETA   * lg2_(parFC);
        const float nBElg2LP = -parBETAET * lg2_(parLP * parFC);
        const float k0uzl    = parK0 * parUZL;

        float SP = 0.001f, MW = 0.001f, SM = 0.001f, SUZ = 0.001f, SLZ = 0.001f;
        float sw = fminf(ex2_(fmaf(parBETA, lg2_(SM), nBlg2FC)), 1.0f);
        float pQ0 = 0.0f, pQ1 = 0.0f, pQ2 = 0.0f;
        const int c3 = cidx * 3;

        for (int k = 0; k <= NCHUNK; k++) {
            __syncthreads();                  // staging + ring handoff
            if (k >= NCHUNK) break;
            const int sb = k % SBN;
            const int qb = k & 1;

            #pragma unroll
            for (int u = 0; u < CH; u++) {
                const float P   = sbuf[sb][u][c3 + 0];
                const float Tt  = sbuf[sb][u][c3 + 1];
                const float PET = sbuf[sb][u][c3 + 2];

                // ---- snow chain (merged melt/refreeze) ----
                const float d    = Tt - parTT;
                const float RAIN = (d >= 0.0f) ? P : 0.0f;
                const float SNOW = P - RAIN;
                const float md   = parCFMAX * d;
                const float xr   = fmaxf(md, parCFR * md);
                const float sp0  = SP + SNOW;
                const float x    = fminf(fmaxf(xr, -MW), sp0);
                const float sp1  = sp0 - x;
                const float mw1  = MW + x;
                const float tosoil = fmaxf(fmaf(-parCWH, sp1, mw1), 0.0f);
                MW = mw1 - tosoil;
                SP = sp1;

                // ---- soil moisture (sw carried from previous step) ----
                const float rt   = RAIN + tosoil;
                const float recharge = rt * sw;
                const float SM1 = fmaf(-rt, sw, SM + rt);
                const float excess = fmaxf(SM1 - parFC, 0.0f);
                const float SM2 = fminf(SM1, parFC);
                // capillary, chain-refactored:
                //   q = cSLZ/FC, SM2+cap = SM2*(1-q) + cSLZ  (cSLZ, q off-chain)
                const float cSLZ = parC * SLZ;
                const float q    = cSLZ * inv_fc;
                const float t1q  = 1.0f - q;
                const float SM3  = fmaxf(fmaf(SM2, t1q, cSLZ), NEARZERO);
                const float cap  = cSLZ * fmaf(-inv_fc, SM2, 1.0f);   // off-chain branch
                const float SLZa = fmaxf(SLZ - cap, NEARZERO);

                // ---- evapfactor pow ----
                const float ef_raw = ex2_(fmaf(parBETAET, lg2_(SM3), nBElg2LP));

                // ==== FILL pow shadow: publish PREVIOUS step's Qs ====
                if (u > 0) {
                    qring[qb][u - 1][c3 + 0] = pQ0;
                    qring[qb][u - 1][c3 + 1] = pQ1;
                    qring[qb][u - 1][c3 + 2] = pQ2;
                }

                // ---- ET & SM (ET-min folded into outer max) ----
                const float ef = fminf(ef_raw, 1.0f);
                SM = fmaxf(fmaf(-PET, ef, SM3), NEARZERO);

                // ---- next step's soil-wetness pow ----
                sw = fminf(ex2_(fmaf(parBETA, lg2_(SM), nBlg2FC)), 1.0f);

                // ==== FILL: response routine (independent of sw) ====
                float suz = SUZ + recharge + excess;
                const float perc = fminf(suz, parPERC);
                suz -= perc;
                const float Q0 = fmaxf(fmaf(parK0, suz, -k0uzl), 0.0f);
                suz -= Q0;
                const float Q1 = parK1 * suz;
                SUZ = suz - Q1;
                float slz = SLZa + perc;
                const float Q2 = parK2 * slz;
                SLZ = slz - Q2;

                pQ0 = Q0; pQ1 = Q1; pQ2 = Q2;
            }
            // flush final step of this chunk into the ring
            qring[qb][CH - 1][c3 + 0] = pQ0;
            qring[qb][CH - 1][c3 + 1] = pQ1;
            qring[qb][CH - 1][c3 + 2] = pQ2;
        }
    } else {
        // ============ ROUTER: staging + 15-tap UH conv (SMSP 2-3) ============
        const int cidx = tid - 64;            // 0..63
        const int g    = g0 + cidx;
        const float* pr = params + ((size_t)(NSTEPS - 1) * NGRID + (size_t)g) * 16;
        float4 r3 = *(const float4*)(pr + 12);
        const float route_a = sigmoidf_(r3.z) * 2.9f;
        const float route_b = sigmoidf_(r3.w) * 6.5f;
        const float aa    = fmaxf(route_a, 0.0f) + 0.1f;
        const float theta = fmaxf(route_b, 0.0f) + 0.5f;
        const float am1   = aa - 1.0f;
        const float invth = __fdividef(1.0f, theta);

        float w[UHL];
        float wsum = 0.0f;
        #pragma unroll
        for (int k = 0; k < UHL; k++) {
            float tk = (float)k + 0.5f;
            float v  = __expf(am1 * __logf(tk) - tk * invth);
            w[k] = v;
            wsum += v;
        }
        const float inv_wsum = __fdividef(1.0f, wsum);
        #pragma unroll
        for (int k = 0; k < UHL; k++) w[k] *= inv_wsum;

        float a0[UHL - 1], a1[UHL - 1], a2[UHL - 1];
        #pragma unroll
        for (int j = 0; j < UHL - 1; j++) { a0[j] = 0.0f; a1[j] = 0.0f; a2[j] = 0.0f; }

        float4* __restrict__ out4 = (float4*)out;
        const int c3 = cidx * 3;

        // prologue: stage chunks 0 and 1
        issue_chunk(xphy, 0, g0, cidx, sbase);
        issue_chunk(xphy, 1, g0, cidx, sbase);

        for (int k = 0; k <= NCHUNK; k++) {
            if (k < NCHUNK) cp_wait1();       // chunk k staged before the barrier
            __syncthreads();
            // stage chunk k+2 into buffer (k+2)%3 (read by producers in window k-1, done)
            if (k + 2 < NCHUNK)
                issue_chunk(xphy, k + 2, g0, cidx, sbase);

            if (k < 1) continue;              // qring for chunk k-1 ready after barrier k
            const int c  = k - 1;
            const int qb = c & 1;
            const int t0 = c * CH;

            #pragma unroll
            for (int u = 0; u < CH; u++) {
                const float q0 = qring[qb][u][c3 + 0];
                const float q1 = qring[qb][u][c3 + 1];
                const float q2 = qring[qb][u][c3 + 2];

                const float y0 = a0[0] + w[0] * q0;
                const float y1 = a1[0] + w[0] * q1;
                const float y2 = a2[0] + w[0] * q2;
                #pragma unroll
                for (int j = 0; j < UHL - 2; j++) {
                    a0[j] = a0[j + 1] + w[j + 1] * q0;
                    a1[j] = a1[j + 1] + w[j + 1] * q1;
                    a2[j] = a2[j + 1] + w[j + 1] * q2;
                }
                a0[UHL - 2] = w[UHL - 1] * q0;
                a1[UHL - 2] = w[UHL - 1] * q1;
                a2[UHL - 2] = w[UHL - 1] * q2;

                float4 o;
                o.x = y0 + y1 + y2;
                o.y = y0;
                o.z = y1;
                o.w = y2;
                out4[(size_t)(t0 + u) * NGRID + g] = o;
            }
        }
    }
}

extern "C" void kernel_launch(void* const* d_in, const int* in_sizes, int n_in,
                              void* d_out, int out_size) {
    const float* xphy   = (const float*)d_in[0];   // [730, 8000, 3]
    const float* params = (const float*)d_in[1];   // [730, 8000, 16]
    float* out = (float*)d_out;                    // [730, 8000, 4]
    (void)in_sizes; (void)n_in; (void)out_size;

    dim3 block(BT);
    dim3 grid(NGRID / CELLS);   // 125 blocks: 4 warps each on 4 SMSPs
    hbv_kernel<<<grid, block>>>(xphy, params, out);
}